// round 1
// baseline (speedup 1.0000x reference)
#include <cuda_runtime.h>
#include <cstddef>

#define NPTS 100000
#define KNN 20

// ---------------- device scratch (allocation-free rule: static __device__) -------------
__device__ int   g_idx64;                       // 1 if neighbor_indices are int64
__device__ float g_w1T[3 * 3 * 64];             // [scale][c][d]
__device__ float g_w2T[3 * 64 * 128];           // [scale][k][d]
__device__ float g_w3T[3 * 128 * 256];          // [scale][k][d]
__device__ float g_sw1T[768 * 256];             // [k][d]
__device__ float g_sw2T[256 * 128];
__device__ float g_sw3T[128 * 64];
__device__ float g_sw4T[64 * 32];
__device__ float g_feats[(size_t)NPTS * 768];   // concat of per-scale pooled features

__device__ __forceinline__ float lrelu(float x) { return fmaxf(x, 0.2f * x); }

// ---------------- dtype detection: int64 indices have zero odd 32-bit words -----------
__global__ void detect_kernel(const unsigned int* __restrict__ raw) {
    __shared__ int flag;
    if (threadIdx.x == 0) flag = 0;
    __syncthreads();
    if (raw[2 * threadIdx.x + 1] != 0u) atomicOr(&flag, 1);
    __syncthreads();
    if (threadIdx.x == 0) g_idx64 = (flag == 0) ? 1 : 0;
}

// ---------------- weight pre-transpose into [k][d] layouts ----------------------------
__global__ void prep_kernel(const float* __restrict__ pw1, const float* __restrict__ pw2,
                            const float* __restrict__ pw3, const float* __restrict__ sw1,
                            const float* __restrict__ sw2, const float* __restrict__ sw3,
                            const float* __restrict__ sw4) {
    const int tid = blockIdx.x * blockDim.x + threadIdx.x;
    const int stride = gridDim.x * blockDim.x;
    for (int i = tid; i < 3 * 3 * 64; i += stride) {
        int s = i / 192, r = i % 192, c = r / 64, d = r % 64;
        g_w1T[i] = pw1[s * 192 + d * 3 + c];
    }
    for (int i = tid; i < 3 * 64 * 128; i += stride) {
        int s = i / 8192, r = i % 8192, k = r / 128, d = r % 128;
        g_w2T[i] = pw2[s * 8192 + d * 64 + k];
    }
    for (int i = tid; i < 3 * 128 * 256; i += stride) {
        int s = i / 32768, r = i % 32768, k = r >> 8, d = r & 255;
        g_w3T[i] = pw3[s * 32768 + d * 128 + k];
    }
    for (int i = tid; i < 768 * 256; i += stride) {
        int k = i >> 8, d = i & 255;
        g_sw1T[i] = sw1[d * 768 + k];
    }
    for (int i = tid; i < 256 * 128; i += stride) {
        int k = i >> 7, d = i & 127;
        g_sw2T[i] = sw2[d * 256 + k];
    }
    for (int i = tid; i < 128 * 64; i += stride) {
        int k = i >> 6, d = i & 63;
        g_sw3T[i] = sw3[d * 128 + k];
    }
    for (int i = tid; i < 64 * 32; i += stride) {
        int k = i >> 5, d = i & 31;
        g_sw4T[i] = sw4[d * 64 + k];
    }
}

// ---------------- fused patch PointNet + max-pool, one scale per template -------------
// Block: 512 threads, persistent over point-tiles. Tile = 40 (point,neighbor) rows.
// P points per tile (P = 40/S). smem holds this scale's full weights + activations.
template <int SI>
__global__ void __launch_bounds__(512) patch_kernel(
    const float* __restrict__ points, const void* __restrict__ nbr,
    const float* __restrict__ pb1, const float* __restrict__ pb2,
    const float* __restrict__ pb3) {
    constexpr int S   = (SI == 0) ? 5 : (SI == 1 ? 10 : 20);
    constexpr int P   = 40 / S;
    constexpr int GPP = S / 5;  // row-groups per point

    extern __shared__ float sm[];
    float* w1   = sm;            // 192
    float* w2   = w1 + 192;      // 8192
    float* w3   = w2 + 8192;     // 32768
    float* b1   = w3 + 32768;    // 64
    float* b2   = b1 + 64;       // 128
    float* b3   = b2 + 128;      // 256
    float* nbs  = b3 + 256;      // 40*4
    float* h1s  = nbs + 160;     // 40*64
    float* h2s  = h1s + 2560;    // 40*128
    float* part = h2s + 5120;    // 8*256

    const int t = threadIdx.x;
    for (int i = t; i < 192; i += 512) w1[i] = g_w1T[SI * 192 + i];
    for (int i = t; i < 2048; i += 512)
        ((float4*)w2)[i] = ((const float4*)(g_w2T + SI * 8192))[i];
    for (int i = t; i < 8192; i += 512)
        ((float4*)w3)[i] = ((const float4*)(g_w3T + SI * 32768))[i];
    if (t < 64)  b1[t] = pb1[SI * 64 + t];
    if (t < 128) b2[t] = pb2[SI * 128 + t];
    if (t < 256) b3[t] = pb3[SI * 256 + t];
    __syncthreads();

    const int dg = t & 63;    // 64 dim-groups
    const int rg = t >> 6;    // 8 row-groups of 5 rows
    const int is64 = g_idx64;
    const int ntiles = NPTS / P;

    for (int tile = blockIdx.x; tile < ntiles; tile += gridDim.x) {
        const int pt0 = tile * P;

        // gather + center: 40 rows
        if (t < 40) {
            const int r = t;
            const int pp = r / S, j = r - pp * S;
            const int p = pt0 + pp;
            long long gi = is64 ? ((const long long*)nbr)[p * KNN + j]
                                : (long long)((const int*)nbr)[p * KNN + j];
            const float* q = points + gi * 3;
            const float* c = points + p * 3;
            nbs[r * 4 + 0] = q[0] - c[0];
            nbs[r * 4 + 1] = q[1] - c[1];
            nbs[r * 4 + 2] = q[2] - c[2];
        }
        __syncthreads();

        // L1: 3 -> 64 (+ leaky)
#pragma unroll
        for (int ii = 0; ii < 5; ii++) {
            int idx = t + ii * 512;  // < 2560
            int d = idx & 63, r = idx >> 6;
            float v = b1[d] + nbs[r * 4 + 0] * w1[d] + nbs[r * 4 + 1] * w1[64 + d] +
                      nbs[r * 4 + 2] * w1[128 + d];
            h1s[r * 64 + d] = lrelu(v);
        }
        __syncthreads();

        // L2: 64 -> 128 (+ leaky); thread tile: 2 dims x 5 rows
        {
            const int d0 = dg * 2, r0 = rg * 5;
            float acc0[5] = {0, 0, 0, 0, 0}, acc1[5] = {0, 0, 0, 0, 0};
#pragma unroll 8
            for (int k = 0; k < 64; k++) {
                float2 w = *(const float2*)(w2 + k * 128 + d0);
#pragma unroll
                for (int j = 0; j < 5; j++) {
                    float a = h1s[(r0 + j) * 64 + k];
                    acc0[j] += w.x * a;
                    acc1[j] += w.y * a;
                }
            }
#pragma unroll
            for (int j = 0; j < 5; j++) {
                float2 st;
                st.x = lrelu(acc0[j] + b2[d0]);
                st.y = lrelu(acc1[j] + b2[d0 + 1]);
                *(float2*)(h2s + (r0 + j) * 128 + d0) = st;
            }
        }
        __syncthreads();

        // L3: 128 -> 256 (no activation); thread tile: 4 dims x 5 rows; local row-max
        {
            const int d0 = dg * 4, r0 = rg * 5;
            float acc[4][5];
#pragma unroll
            for (int i = 0; i < 4; i++)
#pragma unroll
                for (int j = 0; j < 5; j++) acc[i][j] = 0.f;

            for (int k4 = 0; k4 < 128; k4 += 4) {
                float4 a4[5];
#pragma unroll
                for (int j = 0; j < 5; j++)
                    a4[j] = *(const float4*)(h2s + (r0 + j) * 128 + k4);
#pragma unroll
                for (int kk = 0; kk < 4; kk++) {
                    float4 w = *(const float4*)(w3 + (k4 + kk) * 256 + d0);
#pragma unroll
                    for (int j = 0; j < 5; j++) {
                        float a = (kk == 0) ? a4[j].x
                                : (kk == 1) ? a4[j].y
                                : (kk == 2) ? a4[j].z : a4[j].w;
                        acc[0][j] += w.x * a;
                        acc[1][j] += w.y * a;
                        acc[2][j] += w.z * a;
                        acc[3][j] += w.w * a;
                    }
                }
            }
            float mm[4];
#pragma unroll
            for (int i = 0; i < 4; i++) {
                float v = acc[i][0];
#pragma unroll
                for (int j = 1; j < 5; j++) v = fmaxf(v, acc[i][j]);
                mm[i] = v;
            }
            float4 m;
            m.x = mm[0]; m.y = mm[1]; m.z = mm[2]; m.w = mm[3];
            *(float4*)(part + rg * 256 + d0) = m;
        }
        __syncthreads();

        // cross-row-group max per point + bias, write to feats slice
        for (int idx = t; idx < P * 256; idx += 512) {
            int pp = idx >> 8, d = idx & 255;
            float m = part[(pp * GPP) * 256 + d];
#pragma unroll
            for (int g = 1; g < GPP; g++) m = fmaxf(m, part[(pp * GPP + g) * 256 + d]);
            g_feats[(size_t)(pt0 + pp) * 768 + SI * 256 + d] = m + b3[d];
        }
        __syncthreads();
    }
}

// ---------------- shared MLP: 768 -> 256 -> 128 -> 64 -> 32 -> 1 ----------------------
// Block: 256 threads, 32 points. Activations in smem (one overlaid region),
// weights streamed from L2 (pre-transposed).
__global__ void __launch_bounds__(256) mlp_kernel(
    const float* __restrict__ sb1, const float* __restrict__ sb2,
    const float* __restrict__ sb3, const float* __restrict__ sb4,
    const float* __restrict__ sw5, const float* __restrict__ sb5,
    float* __restrict__ out) {
    extern __shared__ float A[];  // 24576 floats
    const int t = threadIdx.x;
    const int pt0 = blockIdx.x * 32;

    {
        const float4* src = (const float4*)(g_feats + (size_t)pt0 * 768);
        for (int i = t; i < 6144; i += 256) ((float4*)A)[i] = src[i];
    }
    __syncthreads();

    const int dg = t & 31;  // 32 dim-groups
    const int rg = t >> 5;  // 8 row-groups of 4 rows (one warp per row-group)
    const int r0 = rg * 4;

    // L1: 768 -> 256 ; dims dg*4..+3 and 128+dg*4..+3
    float h1v[8][4];
    {
        float acc[8][4];
#pragma unroll
        for (int i = 0; i < 8; i++)
#pragma unroll
            for (int j = 0; j < 4; j++) acc[i][j] = 0.f;
#pragma unroll 4
        for (int k = 0; k < 768; k++) {
            float4 wa = *(const float4*)(g_sw1T + k * 256 + dg * 4);
            float4 wb = *(const float4*)(g_sw1T + k * 256 + 128 + dg * 4);
#pragma unroll
            for (int j = 0; j < 4; j++) {
                float a = A[(r0 + j) * 768 + k];
                acc[0][j] += wa.x * a; acc[1][j] += wa.y * a;
                acc[2][j] += wa.z * a; acc[3][j] += wa.w * a;
                acc[4][j] += wb.x * a; acc[5][j] += wb.y * a;
                acc[6][j] += wb.z * a; acc[7][j] += wb.w * a;
            }
        }
#pragma unroll
        for (int i = 0; i < 4; i++)
#pragma unroll
            for (int j = 0; j < 4; j++) {
                h1v[i][j]     = lrelu(acc[i][j] + sb1[dg * 4 + i]);
                h1v[4 + i][j] = lrelu(acc[4 + i][j] + sb1[128 + dg * 4 + i]);
            }
    }
    __syncthreads();  // everyone done reading x
#pragma unroll
    for (int j = 0; j < 4; j++)
#pragma unroll
        for (int i = 0; i < 4; i++) {
            A[(r0 + j) * 256 + dg * 4 + i]       = h1v[i][j];
            A[(r0 + j) * 256 + 128 + dg * 4 + i] = h1v[4 + i][j];
        }
    __syncthreads();

    // L2: 256 -> 128 ; h2 at A[8192]
    {
        float acc[4][4];
#pragma unroll
        for (int i = 0; i < 4; i++)
#pragma unroll
            for (int j = 0; j < 4; j++) acc[i][j] = 0.f;
#pragma unroll 4
        for (int k = 0; k < 256; k++) {
            float4 w = *(const float4*)(g_sw2T + k * 128 + dg * 4);
#pragma unroll
            for (int j = 0; j < 4; j++) {
                float a = A[(r0 + j) * 256 + k];
                acc[0][j] += w.x * a; acc[1][j] += w.y * a;
                acc[2][j] += w.z * a; acc[3][j] += w.w * a;
            }
        }
#pragma unroll
        for (int j = 0; j < 4; j++)
#pragma unroll
            for (int i = 0; i < 4; i++)
                A[8192 + (r0 + j) * 128 + dg * 4 + i] = lrelu(acc[i][j] + sb2[dg * 4 + i]);
    }
    __syncwarp();

    // L3: 128 -> 64 ; h3 at A[12288]
    {
        float acc[2][4];
#pragma unroll
        for (int i = 0; i < 2; i++)
#pragma unroll
            for (int j = 0; j < 4; j++) acc[i][j] = 0.f;
#pragma unroll 4
        for (int k = 0; k < 128; k++) {
            float2 w = *(const float2*)(g_sw3T + k * 64 + dg * 2);
#pragma unroll
            for (int j = 0; j < 4; j++) {
                float a = A[8192 + (r0 + j) * 128 + k];
                acc[0][j] += w.x * a;
                acc[1][j] += w.y * a;
            }
        }
#pragma unroll
        for (int j = 0; j < 4; j++)
#pragma unroll
            for (int i = 0; i < 2; i++)
                A[12288 + (r0 + j) * 64 + dg * 2 + i] = lrelu(acc[i][j] + sb3[dg * 2 + i]);
    }
    __syncwarp();

    // L4: 64 -> 32 ; h4 at A[14336]
    {
        float acc[4] = {0, 0, 0, 0};
#pragma unroll 8
        for (int k = 0; k < 64; k++) {
            float w = g_sw4T[k * 32 + dg];
#pragma unroll
            for (int j = 0; j < 4; j++) acc[j] += w * A[12288 + (r0 + j) * 64 + k];
        }
#pragma unroll
        for (int j = 0; j < 4; j++)
            A[14336 + (r0 + j) * 32 + dg] = lrelu(acc[j] + sb4[dg]);
    }
    __syncthreads();

    // L5: 32 -> 1
    if (t < 32) {
        const int r = t;
        float s = sb5[0];
#pragma unroll
        for (int k = 0; k < 32; k++) s += A[14336 + r * 32 + k] * __ldg(sw5 + k);
        out[pt0 + r] = s;
    }
}

// ---------------- launch --------------------------------------------------------------
extern "C" void kernel_launch(void* const* d_in, const int* in_sizes, int n_in,
                              void* d_out, int out_size) {
    (void)out_size;
    // Resolve inputs by element count (robust to input ordering). All sizes unique
    // except sb4/sw5 (both 32), whose relative order is sb4-first in every candidate
    // ordering, handled by first-match-consumed scanning.
    const int want[18] = {300000, 2000000, 576, 192, 24576, 384, 98304, 768,
                          196608, 256,    32768, 128, 8192, 64,  2048,  32, 32, 1};
    const void* ptr[18] = {};
    {
        int used[64] = {};
        for (int w = 0; w < 18; w++) {
            for (int i = 0; i < n_in && i < 64; i++) {
                if (!used[i] && in_sizes[i] == want[w]) {
                    ptr[w] = d_in[i];
                    used[i] = 1;
                    break;
                }
            }
        }
        for (int w = 0; w < 18; w++)
            if (!ptr[w] && w < n_in) ptr[w] = d_in[w];  // positional fallback
    }

    const float* points = (const float*)ptr[0];
    const void*  nbr    = ptr[1];
    const float* pw1 = (const float*)ptr[2];
    const float* pb1 = (const float*)ptr[3];
    const float* pw2 = (const float*)ptr[4];
    const float* pb2 = (const float*)ptr[5];
    const float* pw3 = (const float*)ptr[6];
    const float* pb3 = (const float*)ptr[7];
    const float* sw1 = (const float*)ptr[8];
    const float* sb1 = (const float*)ptr[9];
    const float* sw2 = (const float*)ptr[10];
    const float* sb2 = (const float*)ptr[11];
    const float* sw3 = (const float*)ptr[12];
    const float* sb3 = (const float*)ptr[13];
    const float* sw4 = (const float*)ptr[14];
    const float* sb4 = (const float*)ptr[15];
    const float* sw5 = (const float*)ptr[16];
    const float* sb5 = (const float*)ptr[17];

    const int SMEM_A = 51488 * 4;  // 205,952 B
    const int SMEM_B = 24576 * 4;  //  98,304 B
    cudaFuncSetAttribute(patch_kernel<0>, cudaFuncAttributeMaxDynamicSharedMemorySize, SMEM_A);
    cudaFuncSetAttribute(patch_kernel<1>, cudaFuncAttributeMaxDynamicSharedMemorySize, SMEM_A);
    cudaFuncSetAttribute(patch_kernel<2>, cudaFuncAttributeMaxDynamicSharedMemorySize, SMEM_A);
    cudaFuncSetAttribute(mlp_kernel, cudaFuncAttributeMaxDynamicSharedMemorySize, SMEM_B);

    detect_kernel<<<1, 256>>>((const unsigned int*)nbr);
    prep_kernel<<<128, 256>>>(pw1, pw2, pw3, sw1, sw2, sw3, sw4);
    patch_kernel<0><<<152, 512, SMEM_A>>>(points, nbr, pb1, pb2, pb3);
    patch_kernel<1><<<152, 512, SMEM_A>>>(points, nbr, pb1, pb2, pb3);
    patch_kernel<2><<<152, 512, SMEM_A>>>(points, nbr, pb1, pb2, pb3);
    mlp_kernel<<<NPTS / 32, 256, SMEM_B>>>(sb1, sb2, sb3, sb4, sw5, sb5, (float*)d_out);
}

// round 3
// speedup vs baseline: 2.1013x; 2.1013x over previous
#include <cuda_runtime.h>
#include <cstddef>
#include <cstdint>

#define NPTS 100000
#define KNN 20

__device__ __forceinline__ float lrelu(float x) { return fmaxf(x, 0.2f * x); }
__device__ __forceinline__ float to_tf32(float x) {
    float r;
    asm("cvt.rna.tf32.f32 %0, %1;" : "=f"(r) : "f"(x));
    return r;
}
// D += A(16x8,row) * B(8x8,col)  tf32
__device__ __forceinline__ void mma8(float* d, const uint4& a, uint32_t b0, uint32_t b1) {
    asm volatile(
        "mma.sync.aligned.m16n8k8.row.col.f32.tf32.tf32.f32 "
        "{%0,%1,%2,%3}, {%4,%5,%6,%7}, {%8,%9}, {%0,%1,%2,%3};"
        : "+f"(d[0]), "+f"(d[1]), "+f"(d[2]), "+f"(d[3])
        : "r"(a.x), "r"(a.y), "r"(a.z), "r"(a.w), "r"(b0), "r"(b1));
}

// ======================= device scratch ================================================
__device__ int   g_idx64;
__device__ float g_w1T[3 * 3 * 64];     // [scale][c][d]
__device__ float g_w2f[3 * 8192];       // W2 B-frag layout, tf32
__device__ float g_w3f[3 * 32768];      // W3 B-frag layout, tf32
__device__ float g_sw1T[768 * 256];
__device__ float g_sw2T[256 * 128];
__device__ float g_sw3T[128 * 64];
__device__ float g_sw4T[64 * 32];
__device__ float g_feats[(size_t)NPTS * 768];

// ---------------- dtype detection: int64 indices have zero odd 32-bit words -----------
__global__ void detect_kernel(const unsigned int* __restrict__ raw) {
    __shared__ int flag;
    if (threadIdx.x == 0) flag = 0;
    __syncthreads();
    if (raw[2 * threadIdx.x + 1] != 0u) atomicOr(&flag, 1);
    __syncthreads();
    if (threadIdx.x == 0) g_idx64 = (flag == 0) ? 1 : 0;
}

// ---------------- weight prep ---------------------------------------------------------
// B-frag (m16n8k8 .col): element (k,n): lane=(n&7)*4+(k&3), reg=(k&4)>>2
__global__ void prep_kernel(const float* __restrict__ pw1, const float* __restrict__ pw2,
                            const float* __restrict__ pw3, const float* __restrict__ sw1,
                            const float* __restrict__ sw2, const float* __restrict__ sw3,
                            const float* __restrict__ sw4) {
    const int tid = blockIdx.x * blockDim.x + threadIdx.x;
    const int stride = gridDim.x * blockDim.x;
    for (int i = tid; i < 3 * 3 * 64; i += stride) {
        int s = i / 192, r = i % 192, c = r / 64, d = r % 64;
        g_w1T[i] = pw1[s * 192 + d * 3 + c];
    }
    // W2: [S][n=128][k=64] -> frag
    for (int i = tid; i < 3 * 128 * 64; i += stride) {
        int s = i >> 13, r = i & 8191, n = r >> 6, k = r & 63;
        float v = to_tf32(pw2[s * 8192 + n * 64 + k]);
        int idx = (((n >> 3) * 8 + (k >> 3)) * 32 + (n & 7) * 4 + (k & 3)) * 2 + ((k & 4) >> 2);
        g_w2f[s * 8192 + idx] = v;
    }
    // W3: [S][n=256][k=128] -> frag
    for (int i = tid; i < 3 * 256 * 128; i += stride) {
        int s = i >> 15, r = i & 32767, n = r >> 7, k = r & 127;
        float v = to_tf32(pw3[s * 32768 + n * 128 + k]);
        int idx = (((n >> 3) * 16 + (k >> 3)) * 32 + (n & 7) * 4 + (k & 3)) * 2 + ((k & 4) >> 2);
        g_w3f[s * 32768 + idx] = v;
    }
    for (int i = tid; i < 768 * 256; i += stride) {
        int k = i >> 8, d = i & 255;
        g_sw1T[i] = sw1[d * 768 + k];
    }
    for (int i = tid; i < 256 * 128; i += stride) {
        int k = i >> 7, d = i & 127;
        g_sw2T[i] = sw2[d * 256 + k];
    }
    for (int i = tid; i < 128 * 64; i += stride) {
        int k = i >> 6, d = i & 63;
        g_sw3T[i] = sw3[d * 128 + k];
    }
    for (int i = tid; i < 64 * 32; i += stride) {
        int k = i >> 5, d = i & 31;
        g_sw4T[i] = sw4[d * 64 + k];
    }
}

// ======================= patch stage: warp mma.sync tf32 ===============================
// Tile = 80 rows. H[rows][dims] = act. C[m=row][n=dim] = A(H) x B(W^T).
// smem float offsets:
#define SF_W3F 0        // 32768
#define SF_H2F 32768    // 10240
#define SF_H1F 43008    // 5120 (aliased by per-warp staging 8*528)
#define SF_NB  48128    // 320
#define SF_W1  48448    // 192
#define SF_B1  48640    // 64
#define SF_B2  48704    // 128
#define SF_TOT 48832
#define SMEM_PATCH (SF_TOT * 4)

template <int SI>
__global__ void __launch_bounds__(256) patch_kernel(
    const float* __restrict__ points, const void* __restrict__ nbr,
    const float* __restrict__ pb1, const float* __restrict__ pb2,
    const float* __restrict__ pb3) {
    constexpr int S = (SI == 0) ? 5 : (SI == 1 ? 10 : 20);
    constexpr int PTS = 80 / S;
    constexpr int NT = NPTS / PTS;

    extern __shared__ float sm[];
    float* W3F = sm + SF_W3F;
    float* H2F = sm + SF_H2F;
    float* H1F = sm + SF_H1F;
    float* NB  = sm + SF_NB;
    float* W1  = sm + SF_W1;
    float* B1  = sm + SF_B1;
    float* B2  = sm + SF_B2;

    const int t = threadIdx.x;
    const int w = t >> 5, lane = t & 31;

    // ---- CTA init ----
    {
        const float4* src = (const float4*)(g_w3f + SI * 32768);
        for (int i = t; i < 8192; i += 256) ((float4*)W3F)[i] = src[i];
        for (int i = t; i < 192; i += 256) W1[i] = g_w1T[SI * 192 + i];
        if (t < 64) B1[t] = pb1[SI * 64 + t];
        if (t < 128) B2[t] = pb2[SI * 128 + t];
    }
    const float b3v = pb3[SI * 256 + w * 32 + lane];

    // W2 slice in registers: warp w owns dims 16w..16w+15 (ntiles 2w, 2w+1)
    uint32_t bw2[8][2][2];
#pragma unroll
    for (int ks = 0; ks < 8; ks++)
#pragma unroll
        for (int nt = 0; nt < 2; nt++) {
            float2 v = *(const float2*)(g_w2f + SI * 8192 +
                                        (((2 * w + nt) * 8 + ks) * 32 + lane) * 2);
            bw2[ks][nt][0] = __float_as_uint(v.x);
            bw2[ks][nt][1] = __float_as_uint(v.y);
        }
    const int is64 = g_idx64;
    __syncthreads();

    for (int tile = blockIdx.x; tile < NT; tile += gridDim.x) {
        const int pt0 = tile * PTS;

        // ---- gather + center ----
        if (t < 80) {
            const int p = pt0 + t / S, j = t % S;
            long long gi = is64 ? ((const long long*)nbr)[p * KNN + j]
                                : (long long)((const int*)nbr)[p * KNN + j];
            const float* q = points + gi * 3;
            const float* c = points + (long long)p * 3;
            NB[t * 4 + 0] = q[0] - c[0];
            NB[t * 4 + 1] = q[1] - c[1];
            NB[t * 4 + 2] = q[2] - c[2];
        }
        __syncthreads();

        // ---- L1: 3 -> 64 scalar, write A-frag layout ----
#pragma unroll
        for (int ii = 0; ii < 20; ii++) {
            int i = t + ii * 256;  // < 5120
            int d = i & 63, r = i >> 6;
            float v = B1[d] + NB[r * 4] * W1[d] + NB[r * 4 + 1] * W1[64 + d] +
                      NB[r * 4 + 2] * W1[128 + d];
            v = to_tf32(lrelu(v));
            int mt = r >> 4, ks = d >> 3;
            int lf = ((r & 7) << 2) | (d & 3);
            int rg = ((r & 8) >> 3) | ((d & 4) >> 1);
            H1F[((mt * 8 + ks) * 32 + lf) * 4 + rg] = v;
        }
        __syncthreads();

        // ---- L2: C2[80 x 128] = H1 x W2^T (W2 in regs) ----
        float acc2[5][2][4];
#pragma unroll
        for (int mt = 0; mt < 5; mt++)
#pragma unroll
            for (int nt = 0; nt < 2; nt++)
#pragma unroll
                for (int e = 0; e < 4; e++) acc2[mt][nt][e] = 0.f;
#pragma unroll
        for (int ks = 0; ks < 8; ks++) {
#pragma unroll
            for (int mt = 0; mt < 5; mt++) {
                uint4 A = *(const uint4*)(H1F + ((mt * 8 + ks) * 32 + lane) * 4);
#pragma unroll
                for (int nt = 0; nt < 2; nt++)
                    mma8(acc2[mt][nt], A, bw2[ks][nt][0], bw2[ks][nt][1]);
            }
        }
        // L2 epilogue: bias+leaky+tf32 -> H2F (A-frag layout for L3)
#pragma unroll
        for (int mt = 0; mt < 5; mt++)
#pragma unroll
            for (int nt = 0; nt < 2; nt++)
#pragma unroll
                for (int e = 0; e < 4; e++) {
                    int m = mt * 16 + (lane >> 2) + ((e >> 1) << 3);
                    int n = w * 16 + nt * 8 + ((lane & 3) << 1) + (e & 1);
                    float v = to_tf32(lrelu(acc2[mt][nt][e] + B2[n]));
                    int ks = n >> 3;
                    int lf = ((m & 7) << 2) | (n & 3);
                    int rg = ((m & 8) >> 3) | ((n & 4) >> 1);
                    H2F[((mt * 16 + ks) * 32 + lf) * 4 + rg] = v;
                }
        __syncthreads();

        // ---- L3: C3[80 x 256] = H2 x W3^T ----
        float acc3[5][4][4];
#pragma unroll
        for (int mt = 0; mt < 5; mt++)
#pragma unroll
            for (int nt = 0; nt < 4; nt++)
#pragma unroll
                for (int e = 0; e < 4; e++) acc3[mt][nt][e] = 0.f;
#pragma unroll 4
        for (int ks = 0; ks < 16; ks++) {
            uint32_t b[4][2];
#pragma unroll
            for (int nt = 0; nt < 4; nt++) {
                float2 v = *(const float2*)(W3F + (((4 * w + nt) * 16 + ks) * 32 + lane) * 2);
                b[nt][0] = __float_as_uint(v.x);
                b[nt][1] = __float_as_uint(v.y);
            }
#pragma unroll
            for (int mt = 0; mt < 5; mt++) {
                uint4 A = *(const uint4*)(H2F + ((mt * 16 + ks) * 32 + lane) * 4);
#pragma unroll
                for (int nt = 0; nt < 4; nt++) mma8(acc3[mt][nt], A, b[nt][0], b[nt][1]);
            }
        }

        // ---- L3 epilogue: per-warp staging (stride 33) + pooled max + bias ----
        float* stg = H1F + w * 528;
        float cur = -3.4e38f;
#pragma unroll
        for (int mt = 0; mt < 5; mt++) {
            __syncwarp();
#pragma unroll
            for (int nt = 0; nt < 4; nt++)
#pragma unroll
                for (int e = 0; e < 4; e++) {
                    int mr = (lane >> 2) + ((e >> 1) << 3);
                    int nc = nt * 8 + ((lane & 3) << 1) + (e & 1);
                    stg[mr * 33 + nc] = acc3[mt][nt][e];
                }
            __syncwarp();
#pragma unroll
            for (int r = 0; r < 16; r++) {
                cur = fmaxf(cur, stg[r * 33 + lane]);
                int grow = mt * 16 + r;
                if (((grow + 1) % S) == 0) {
                    int pt = grow / S;
                    g_feats[(size_t)(pt0 + pt) * 768 + SI * 256 + w * 32 + lane] = cur + b3v;
                    cur = -3.4e38f;
                }
            }
        }
        __syncthreads();
    }
}

// ======================= shared MLP (proven fp32 version) ==============================
__global__ void __launch_bounds__(256) mlp_kernel(
    const float* __restrict__ sb1, const float* __restrict__ sb2,
    const float* __restrict__ sb3, const float* __restrict__ sb4,
    const float* __restrict__ sw5, const float* __restrict__ sb5,
    float* __restrict__ out) {
    extern __shared__ float A[];
    const int t = threadIdx.x;
    const int pt0 = blockIdx.x * 32;

    {
        const float4* src = (const float4*)(g_feats + (size_t)pt0 * 768);
        for (int i = t; i < 6144; i += 256) ((float4*)A)[i] = src[i];
    }
    __syncthreads();

    const int dg = t & 31;
    const int rg = t >> 5;
    const int r0 = rg * 4;

    float h1v[8][4];
    {
        float acc[8][4];
#pragma unroll
        for (int i = 0; i < 8; i++)
#pragma unroll
            for (int j = 0; j < 4; j++) acc[i][j] = 0.f;
#pragma unroll 4
        for (int k = 0; k < 768; k++) {
            float4 wa = *(const float4*)(g_sw1T + k * 256 + dg * 4);
            float4 wb = *(const float4*)(g_sw1T + k * 256 + 128 + dg * 4);
#pragma unroll
            for (int j = 0; j < 4; j++) {
                float a = A[(r0 + j) * 768 + k];
                acc[0][j] += wa.x * a; acc[1][j] += wa.y * a;
                acc[2][j] += wa.z * a; acc[3][j] += wa.w * a;
                acc[4][j] += wb.x * a; acc[5][j] += wb.y * a;
                acc[6][j] += wb.z * a; acc[7][j] += wb.w * a;
            }
        }
#pragma unroll
        for (int i = 0; i < 4; i++)
#pragma unroll
            for (int j = 0; j < 4; j++) {
                h1v[i][j]     = lrelu(acc[i][j] + sb1[dg * 4 + i]);
                h1v[4 + i][j] = lrelu(acc[4 + i][j] + sb1[128 + dg * 4 + i]);
            }
    }
    __syncthreads();
#pragma unroll
    for (int j = 0; j < 4; j++)
#pragma unroll
        for (int i = 0; i < 4; i++) {
            A[(r0 + j) * 256 + dg * 4 + i]       = h1v[i][j];
            A[(r0 + j) * 256 + 128 + dg * 4 + i] = h1v[4 + i][j];
        }
    __syncthreads();

    {
        float acc[4][4];
#pragma unroll
        for (int i = 0; i < 4; i++)
#pragma unroll
            for (int j = 0; j < 4; j++) acc[i][j] = 0.f;
#pragma unroll 4
        for (int k = 0; k < 256; k++) {
            float4 wv = *(const float4*)(g_sw2T + k * 128 + dg * 4);
#pragma unroll
            for (int j = 0; j < 4; j++) {
                float a = A[(r0 + j) * 256 + k];
                acc[0][j] += wv.x * a; acc[1][j] += wv.y * a;
                acc[2][j] += wv.z * a; acc[3][j] += wv.w * a;
            }
        }
#pragma unroll
        for (int j = 0; j < 4; j++)
#pragma unroll
            for (int i = 0; i < 4; i++)
                A[8192 + (r0 + j) * 128 + dg * 4 + i] = lrelu(acc[i][j] + sb2[dg * 4 + i]);
    }
    __syncwarp();

    {
        float acc[2][4];
#pragma unroll
        for (int i = 0; i < 2; i++)
#pragma unroll
            for (int j = 0; j < 4; j++) acc[i][j] = 0.f;
#pragma unroll 4
        for (int k = 0; k < 128; k++) {
            float2 wv = *(const float2*)(g_sw3T + k * 64 + dg * 2);
#pragma unroll
            for (int j = 0; j < 4; j++) {
                float a = A[8192 + (r0 + j) * 128 + k];
                acc[0][j] += wv.x * a;
                acc[1][j] += wv.y * a;
            }
        }
#pragma unroll
        for (int j = 0; j < 4; j++)
#pragma unroll
            for (int i = 0; i < 2; i++)
                A[12288 + (r0 + j) * 64 + dg * 2 + i] = lrelu(acc[i][j] + sb3[dg * 2 + i]);
    }
    __syncwarp();

    {
        float acc[4] = {0, 0, 0, 0};
#pragma unroll 8
        for (int k = 0; k < 64; k++) {
            float wv = g_sw4T[k * 32 + dg];
#pragma unroll
            for (int j = 0; j < 4; j++) acc[j] += wv * A[12288 + (r0 + j) * 64 + k];
        }
#pragma unroll
        for (int j = 0; j < 4; j++)
            A[14336 + (r0 + j) * 32 + dg] = lrelu(acc[j] + sb4[dg]);
    }
    __syncthreads();

    if (t < 32) {
        const int r = t;
        float s = sb5[0];
#pragma unroll
        for (int k = 0; k < 32; k++) s += A[14336 + r * 32 + k] * __ldg(sw5 + k);
        out[pt0 + r] = s;
    }
}

// ======================= launch ========================================================
extern "C" void kernel_launch(void* const* d_in, const int* in_sizes, int n_in,
                              void* d_out, int out_size) {
    (void)out_size;
    const int want[18] = {300000, 2000000, 576, 192, 24576, 384, 98304, 768,
                          196608, 256,    32768, 128, 8192, 64,  2048,  32, 32, 1};
    const void* ptr[18] = {};
    {
        int used[64] = {};
        for (int w = 0; w < 18; w++) {
            for (int i = 0; i < n_in && i < 64; i++) {
                if (!used[i] && in_sizes[i] == want[w]) {
                    ptr[w] = d_in[i];
                    used[i] = 1;
                    break;
                }
            }
        }
        for (int w = 0; w < 18; w++)
            if (!ptr[w] && w < n_in) ptr[w] = d_in[w];
    }

    const float* points = (const float*)ptr[0];
    const void*  nbr    = ptr[1];
    const float* pw1 = (const float*)ptr[2];
    const float* pb1 = (const float*)ptr[3];
    const float* pw2 = (const float*)ptr[4];
    const float* pb2 = (const float*)ptr[5];
    const float* pw3 = (const float*)ptr[6];
    const float* pb3 = (const float*)ptr[7];
    const float* sw1 = (const float*)ptr[8];
    const float* sb1 = (const float*)ptr[9];
    const float* sw2 = (const float*)ptr[10];
    const float* sb2 = (const float*)ptr[11];
    const float* sw3 = (const float*)ptr[12];
    const float* sb3 = (const float*)ptr[13];
    const float* sw4 = (const float*)ptr[14];
    const float* sb4 = (const float*)ptr[15];
    const float* sw5 = (const float*)ptr[16];
    const float* sb5 = (const float*)ptr[17];

    const int SMEM_B = 24576 * 4;
    cudaFuncSetAttribute(patch_kernel<0>, cudaFuncAttributeMaxDynamicSharedMemorySize, SMEM_PATCH);
    cudaFuncSetAttribute(patch_kernel<1>, cudaFuncAttributeMaxDynamicSharedMemorySize, SMEM_PATCH);
    cudaFuncSetAttribute(patch_kernel<2>, cudaFuncAttributeMaxDynamicSharedMemorySize, SMEM_PATCH);
    cudaFuncSetAttribute(mlp_kernel, cudaFuncAttributeMaxDynamicSharedMemorySize, SMEM_B);

    detect_kernel<<<1, 256>>>((const unsigned int*)nbr);
    prep_kernel<<<128, 256>>>(pw1, pw2, pw3, sw1, sw2, sw3, sw4);
    patch_kernel<0><<<152, 256, SMEM_PATCH>>>(points, nbr, pb1, pb2, pb3);
    patch_kernel<1><<<152, 256, SMEM_PATCH>>>(points, nbr, pb1, pb2, pb3);
    patch_kernel<2><<<152, 256, SMEM_PATCH>>>(points, nbr, pb1, pb2, pb3);
    mlp_kernel<<<NPTS / 32, 256, SMEM_B>>>(sb1, sb2, sb3, sb4, sw5, sb5, (float*)d_out);
}